// round 7
// baseline (speedup 1.0000x reference)
#include <cuda_runtime.h>
#include <math.h>

// Shapes (fixed by setup_inputs): B=4, N=64, T=64, FH=128, FO=64
#define N_  64
#define T_  64
#define FH_ 128
#define FO_ 64

// Scratch (device globals; no allocation allowed)
__device__ float g_wh[4 * N_ * T_ * FO_];   // Wh[b][n][t][o]
__device__ float g_pr[4 * N_ * T_];         // pr[b][t][n]  (t-major for main kernel)
__device__ float g_ps[4 * N_ * T_];
__device__ float g_wr[FH_];
__device__ float g_ws[FH_];
__device__ float g_cr;
__device__ float g_cs;
__device__ float g_cnt[N_ * N_];

// ---------------------------------------------------------------------------
// packed fp32x2 helpers (Blackwell FFMA2 — only reachable via PTX)
// ---------------------------------------------------------------------------
__device__ __forceinline__ unsigned long long fma2(unsigned long long a,
                                                   unsigned long long b,
                                                   unsigned long long c) {
    unsigned long long d;
    asm("fma.rn.f32x2 %0, %1, %2, %3;" : "=l"(d) : "l"(a), "l"(b), "l"(c));
    return d;
}
__device__ __forceinline__ unsigned long long pack2(float x, float y) {
    unsigned long long d;
    asm("mov.b64 %0, {%1, %2};" : "=l"(d)
        : "r"(__float_as_uint(x)), "r"(__float_as_uint(y)));
    return d;
}
__device__ __forceinline__ float lo2(unsigned long long v) {
    return __uint_as_float((unsigned)v);
}
__device__ __forceinline__ float hi2(unsigned long long v) {
    return __uint_as_float((unsigned)(v >> 32));
}

// ---------------------------------------------------------------------------
// Kernel 1: prep — fold a_w into W_fc / b_fc ; zero cnt
// ---------------------------------------------------------------------------
__global__ void prep_kernel(const float* __restrict__ W,   // [FO][FH]
                            const float* __restrict__ bfc, // [FO]
                            const float* __restrict__ aw)  // [2*FO]
{
    int k = threadIdx.x; // 0..127
    float wr = 0.f, ws = 0.f;
    #pragma unroll 8
    for (int o = 0; o < FO_; o++) {
        float w = W[o * FH_ + k];
        wr += aw[o] * w;
        ws += aw[FO_ + o] * w;
    }
    g_wr[k] = wr;
    g_ws[k] = ws;
    if (k == 0) {
        float c = 0.f;
        for (int o = 0; o < FO_; o++) c += aw[o] * bfc[o];
        g_cr = c;
    }
    if (k == 1) {
        float c = 0.f;
        for (int o = 0; o < FO_; o++) c += aw[FO_ + o] * bfc[o];
        g_cs = c;
    }
    for (int i = 0; i < 32; i++) g_cnt[k + i * 128] = 0.f;
}

// ---------------------------------------------------------------------------
// Kernel 2: edge multiplicity via argmax (float4 loads, first-max rule)
// ---------------------------------------------------------------------------
__global__ void edge_kernel(const float* __restrict__ rr,
                            const float* __restrict__ rs, int E)
{
    int e = blockIdx.x * blockDim.x + threadIdx.x;
    if (e >= E) return;
    const float4* r4 = reinterpret_cast<const float4*>(rr) + (size_t)e * 16;
    const float4* s4 = reinterpret_cast<const float4*>(rs) + (size_t)e * 16;
    float mr = -1e30f, ms = -1e30f;
    int ir = 0, is = 0;
    #pragma unroll
    for (int j = 0; j < 16; j++) {
        float4 v = r4[j];
        if (v.x > mr) { mr = v.x; ir = j * 4 + 0; }
        if (v.y > mr) { mr = v.y; ir = j * 4 + 1; }
        if (v.z > mr) { mr = v.z; ir = j * 4 + 2; }
        if (v.w > mr) { mr = v.w; ir = j * 4 + 3; }
        float4 w = s4[j];
        if (w.x > ms) { ms = w.x; is = j * 4 + 0; }
        if (w.y > ms) { ms = w.y; is = j * 4 + 1; }
        if (w.z > ms) { ms = w.z; is = j * 4 + 2; }
        if (w.w > ms) { ms = w.w; is = j * 4 + 3; }
    }
    atomicAdd(&g_cnt[ir * N_ + is], 1.0f);
}

// ---------------------------------------------------------------------------
// Kernel 3: Wh = h @ W^T + b, plus pr/ps projections.
// Block = (t-half, n, b): grid 512, 128 threads, 16 outputs/thread (FFMA2).
// dyn smem: sh_h[32][132] + sh_Wt[128][68]  = 51.7 KB -> 4 blocks/SM
// ---------------------------------------------------------------------------
#define SHH_STRIDE 132
#define SWT_STRIDE 68

__global__ void __launch_bounds__(128, 4)
wh_kernel(const float* __restrict__ h,    // [B][N][T][FH]
          const float* __restrict__ W,    // [FO][FH]
          const float* __restrict__ bfc)  // [FO]
{
    extern __shared__ float smem[];
    float* sh_h  = smem;                        // 32*132
    float* sh_Wt = smem + 32 * SHH_STRIDE;      // 128*68 (k-major, padded)

    const int th  = blockIdx.x;   // t-half: 0/1
    const int n   = blockIdx.y;
    const int b   = blockIdx.z;
    const int tid = threadIdx.x;

    // stage h half-tile (32 t rows), float4, t-major
    {
        const float4* hb4 = reinterpret_cast<const float4*>(
            h + (((size_t)(b * N_ + n)) * T_ + th * 32) * FH_);
        #pragma unroll
        for (int i = 0; i < 8; i++) {
            int j = tid + i * 128;
            int t = j >> 5, k4 = (j & 31) * 4;
            *reinterpret_cast<float4*>(&sh_h[t * SHH_STRIDE + k4]) = hb4[j];
        }
    }
    // stage W transposed -> [k][o]
    {
        int o  = tid >> 1;            // 0..63
        int kc = (tid & 1) * 64;      // 0 / 64
        const float4* wrow = reinterpret_cast<const float4*>(W + o * FH_ + kc);
        #pragma unroll
        for (int j = 0; j < 16; j++) {
            float4 v = wrow[j];
            int k = kc + j * 4;
            sh_Wt[(k + 0) * SWT_STRIDE + o] = v.x;
            sh_Wt[(k + 1) * SWT_STRIDE + o] = v.y;
            sh_Wt[(k + 2) * SWT_STRIDE + o] = v.z;
            sh_Wt[(k + 3) * SWT_STRIDE + o] = v.w;
        }
    }
    __syncthreads();

    // GEMM: thread (tloc = tid>>2 in 0..31, og = tid&3), o = og*4 + c*16 + j
    const int tloc = tid >> 2;
    const int og   = tid & 3;

    unsigned long long acc[8];
    #pragma unroll
    for (int c = 0; c < 4; c++) {
        int o0 = og * 4 + c * 16;
        acc[2 * c + 0] = pack2(bfc[o0 + 0], bfc[o0 + 1]);
        acc[2 * c + 1] = pack2(bfc[o0 + 2], bfc[o0 + 3]);
    }

    const float* hrow = sh_h + tloc * SHH_STRIDE;
    #pragma unroll 4
    for (int k = 0; k < FH_; k++) {
        float hv = hrow[k];
        unsigned long long hh = pack2(hv, hv);
        const float* wk = sh_Wt + k * SWT_STRIDE + og * 4;
        #pragma unroll
        for (int c = 0; c < 4; c++) {
            ulonglong2 w = *reinterpret_cast<const ulonglong2*>(wk + c * 16);
            acc[2 * c + 0] = fma2(hh, w.x, acc[2 * c + 0]);
            acc[2 * c + 1] = fma2(hh, w.y, acc[2 * c + 1]);
        }
    }

    float* out = g_wh + (((size_t)(b * N_ + n)) * T_ + th * 32 + tloc) * FO_;
    #pragma unroll
    for (int c = 0; c < 4; c++) {
        float4 v = make_float4(lo2(acc[2 * c]), hi2(acc[2 * c]),
                               lo2(acc[2 * c + 1]), hi2(acc[2 * c + 1]));
        *reinterpret_cast<float4*>(out + og * 4 + c * 16) = v;
    }

    // pr / ps projections for the 32 t rows in this half
    if (tid < 64) {
        int tt = tid & 31;
        const float* hr = sh_h + tt * SHH_STRIDE;
        int tg = th * 32 + tt;
        if (tid < 32) {
            float a = g_cr;
            #pragma unroll 8
            for (int k = 0; k < FH_; k++) a = fmaf(hr[k], g_wr[k], a);
            g_pr[b * (T_ * N_) + tg * N_ + n] = a;
        } else {
            float a = g_cs;
            #pragma unroll 8
            for (int k = 0; k < FH_; k++) a = fmaf(hr[k], g_ws[k], a);
            g_ps[b * (T_ * N_) + tg * N_ + n] = a;
        }
    }
}

// ---------------------------------------------------------------------------
// Kernel 4: fused edge scores -> A / A_sym / A_norm / h_p.
// Block = (n-half, t, b): grid 512, 128 threads. Each block computes the FULL
// 64x64 score tile (needed for A_sym transpose), but writes/normalizes/matmuls
// only its 32 output rows.
// ---------------------------------------------------------------------------
#define SA_STRIDE 65

__global__ void __launch_bounds__(128, 6)
main_kernel(const float* __restrict__ ab_ptr,
            float* __restrict__ out, int B)
{
    __shared__ float sA[N_ * SA_STRIDE];                 // 16640 B
    __shared__ __align__(16) float sWh[N_ * FO_];        // 16384 B
    __shared__ float sPr[N_];
    __shared__ float sPs[N_];
    __shared__ float sInv[32];

    const int nh  = blockIdx.x;   // 0/1
    const int t   = blockIdx.y;
    const int b   = blockIdx.z;
    const int tid = threadIdx.x;
    const float ab = ab_ptr[0];

    if (tid < N_)  sPr[tid] = g_pr[b * (T_ * N_) + t * N_ + tid];
    else           sPs[tid - N_] = g_ps[b * (T_ * N_) + t * N_ + (tid - N_)];
    __syncthreads();

    // full score tile + stage Wh[:,t,:]
    const float* whb = g_wh + (size_t)b * N_ * T_ * FO_ + (size_t)t * FO_;
    #pragma unroll
    for (int i = 0; i < 32; i++) {
        int idx = tid + i * 128;
        int r = idx >> 6, s = idx & 63;
        float c = g_cnt[idx];
        float v = 0.f;
        if (c != 0.f) {
            float x = sPr[r] + sPs[s] + ab;
            x = (x > 0.f) ? x : 0.2f * x;
            v = c * __expf(x);
        }
        sA[r * SA_STRIDE + s] = v;
        sWh[idx] = whb[(size_t)r * (T_ * FO_) + s];   // m=r, o=s
    }
    __syncthreads();

    // row reciprocals for our 32 rows
    if (tid < 32) {
        int r = nh * 32 + tid;
        float sum = 0.f;
        const float* row = sA + r * SA_STRIDE;
        #pragma unroll 8
        for (int s = 0; s < N_; s++) sum += row[s];
        sInv[tid] = __fdividef(1.f, sum);
    }
    __syncthreads();

    const size_t npp = (size_t)B * T_ * N_ * N_;
    float* A_out     = out + (size_t)B * N_ * T_ * FO_;
    float* Asym_out  = A_out + npp;
    float* Anorm_out = Asym_out + npp;
    const size_t abase = ((size_t)(b * T_ + t)) * (N_ * N_) + (size_t)nh * 32 * N_;

    // write A and A_sym for our half (transpose reads need full sA — before normalize)
    #pragma unroll
    for (int i = 0; i < 16; i++) {
        int idx = tid + i * 128;
        int rl = idx >> 6, s = idx & 63;
        int r = nh * 32 + rl;
        float v = sA[r * SA_STRIDE + s];
        A_out[abase + idx]    = v;
        Asym_out[abase + idx] = 0.5f * (v + sA[s * SA_STRIDE + r]);
    }
    __syncthreads();

    // normalize our half in place and write A_norm
    #pragma unroll
    for (int i = 0; i < 16; i++) {
        int idx = tid + i * 128;
        int rl = idx >> 6, s = idx & 63;
        int r = nh * 32 + rl;
        float v = sA[r * SA_STRIDE + s] * sInv[rl];
        Anorm_out[abase + idx] = v;
        sA[r * SA_STRIDE + s] = v;
    }
    __syncthreads();

    // h_p[b,n,t,o] = relu( sum_m A_norm[n,m] * Wh[m,o] )  for n in our half
    const int n  = nh * 32 + (tid >> 2);
    const int og = tid & 3;
    unsigned long long acc[8];
    #pragma unroll
    for (int i = 0; i < 8; i++) acc[i] = 0ull;

    const float* arow = sA + n * SA_STRIDE;
    #pragma unroll 4
    for (int m = 0; m < N_; m++) {
        float a = arow[m];
        unsigned long long aa = pack2(a, a);
        const float* wm = sWh + m * FO_ + og * 4;
        #pragma unroll
        for (int c = 0; c < 4; c++) {
            ulonglong2 w = *reinterpret_cast<const ulonglong2*>(wm + c * 16);
            acc[2 * c + 0] = fma2(aa, w.x, acc[2 * c + 0]);
            acc[2 * c + 1] = fma2(aa, w.y, acc[2 * c + 1]);
        }
    }

    float* hp = out + (size_t)b * (N_ * T_ * FO_) + (size_t)n * (T_ * FO_) + (size_t)t * FO_;
    #pragma unroll
    for (int c = 0; c < 4; c++) {
        float4 v = make_float4(fmaxf(lo2(acc[2 * c]), 0.f),
                               fmaxf(hi2(acc[2 * c]), 0.f),
                               fmaxf(lo2(acc[2 * c + 1]), 0.f),
                               fmaxf(hi2(acc[2 * c + 1]), 0.f));
        *reinterpret_cast<float4*>(hp + og * 4 + c * 16) = v;
    }
}

// ---------------------------------------------------------------------------
extern "C" void kernel_launch(void* const* d_in, const int* in_sizes, int n_in,
                              void* d_out, int out_size)
{
    const float* h   = (const float*)d_in[0];
    const float* rr  = (const float*)d_in[1];
    const float* rs  = (const float*)d_in[2];
    const float* Wfc = (const float*)d_in[3];
    const float* bfc = (const float*)d_in[4];
    const float* aw  = (const float*)d_in[5];
    const float* abp = (const float*)d_in[6];

    const int B = in_sizes[0] / (N_ * T_ * FH_);
    const int E = in_sizes[1] / N_;

    static bool attr_done = false;
    const int wh_smem = (32 * SHH_STRIDE + FH_ * SWT_STRIDE) * sizeof(float);
    if (!attr_done) {
        cudaFuncSetAttribute(wh_kernel, cudaFuncAttributeMaxDynamicSharedMemorySize, wh_smem);
        attr_done = true;
    }

    prep_kernel<<<1, 128>>>(Wfc, bfc, aw);
    edge_kernel<<<(E + 127) / 128, 128>>>(rr, rs, E);
    wh_kernel<<<dim3(2, N_, B), 128, wh_smem>>>(h, Wfc, bfc);
    main_kernel<<<dim3(2, T_, B), 128>>>(abp, (float*)d_out, B);
}

// round 11
// speedup vs baseline: 1.4855x; 1.4855x over previous
#include <cuda_runtime.h>
#include <math.h>

// Shapes (fixed by setup_inputs): B=4, N=64, T=64, FH=128, FO=64
#define N_  64
#define T_  64
#define FH_ 128
#define FO_ 64

// Scratch (device globals; no allocation allowed)
__device__ float g_wr[FH_];
__device__ float g_ws[FH_];
__device__ float g_cr;
__device__ float g_cs;
__device__ float g_cnt[N_ * N_];

// ---------------------------------------------------------------------------
// packed fp32x2 helpers (Blackwell FFMA2 — only reachable via PTX)
// ---------------------------------------------------------------------------
__device__ __forceinline__ unsigned long long fma2(unsigned long long a,
                                                   unsigned long long b,
                                                   unsigned long long c) {
    unsigned long long d;
    asm("fma.rn.f32x2 %0, %1, %2, %3;" : "=l"(d) : "l"(a), "l"(b), "l"(c));
    return d;
}
__device__ __forceinline__ unsigned long long pack2(float x, float y) {
    unsigned long long d;
    asm("mov.b64 %0, {%1, %2};" : "=l"(d)
        : "r"(__float_as_uint(x)), "r"(__float_as_uint(y)));
    return d;
}
__device__ __forceinline__ float lo2(unsigned long long v) {
    return __uint_as_float((unsigned)v);
}
__device__ __forceinline__ float hi2(unsigned long long v) {
    return __uint_as_float((unsigned)(v >> 32));
}

// ---------------------------------------------------------------------------
// Kernel 1: prep — fold a_w into W_fc / b_fc ; zero cnt
// ---------------------------------------------------------------------------
__global__ void prep_kernel(const float* __restrict__ W,   // [FO][FH]
                            const float* __restrict__ bfc, // [FO]
                            const float* __restrict__ aw)  // [2*FO]
{
    int k = threadIdx.x; // 0..127
    float wr = 0.f, ws = 0.f;
    #pragma unroll 8
    for (int o = 0; o < FO_; o++) {
        float w = W[o * FH_ + k];
        wr += aw[o] * w;
        ws += aw[FO_ + o] * w;
    }
    g_wr[k] = wr;
    g_ws[k] = ws;
    if (k == 0) {
        float c = 0.f;
        for (int o = 0; o < FO_; o++) c += aw[o] * bfc[o];
        g_cr = c;
    }
    if (k == 1) {
        float c = 0.f;
        for (int o = 0; o < FO_; o++) c += aw[FO_ + o] * bfc[o];
        g_cs = c;
    }
    for (int i = 0; i < 32; i++) g_cnt[k + i * 128] = 0.f;
}

// ---------------------------------------------------------------------------
// Kernel 2: edge multiplicity via argmax (float4 loads, first-max rule)
// ---------------------------------------------------------------------------
__global__ void edge_kernel(const float* __restrict__ rr,
                            const float* __restrict__ rs, int E)
{
    int e = blockIdx.x * blockDim.x + threadIdx.x;
    if (e >= E) return;
    const float4* r4 = reinterpret_cast<const float4*>(rr) + (size_t)e * 16;
    const float4* s4 = reinterpret_cast<const float4*>(rs) + (size_t)e * 16;
    float mr = -1e30f, ms = -1e30f;
    int ir = 0, is = 0;
    #pragma unroll
    for (int j = 0; j < 16; j++) {
        float4 v = r4[j];
        if (v.x > mr) { mr = v.x; ir = j * 4 + 0; }
        if (v.y > mr) { mr = v.y; ir = j * 4 + 1; }
        if (v.z > mr) { mr = v.z; ir = j * 4 + 2; }
        if (v.w > mr) { mr = v.w; ir = j * 4 + 3; }
        float4 w = s4[j];
        if (w.x > ms) { ms = w.x; is = j * 4 + 0; }
        if (w.y > ms) { ms = w.y; is = j * 4 + 1; }
        if (w.z > ms) { ms = w.z; is = j * 4 + 2; }
        if (w.w > ms) { ms = w.w; is = j * 4 + 3; }
    }
    atomicAdd(&g_cnt[ir * N_ + is], 1.0f);
}

// ---------------------------------------------------------------------------
// Kernel 3: FUSED. One block per (b,t), 128 threads.
//   Phase 1: stage h[b,:,t,:] (64n x 128k) + W^T (128k x 64o) + wr/ws
//   Phase 2: pr/ps (rank-1 dots) ; GEMM1: Wh = h @ W^T + b  -> smem
//   Phase 3: scores -> sA ; row sums
//   Phase 4: write A, A_sym ; normalize in place -> A_norm
//   Phase 5: GEMM2: h_p = relu(A_norm @ Wh)
// smem offsets (floats):
//   sh  [64][132]  @0       (8448)
//   swt [128][68]  @8448    (8704)
//   sa  [64][68]   @17152   (4352)   (also holds wr/ws in phase 1-2)
//   swh [64][68]   @21504   (4352)
//   spr [64] @25856, sps [64] @25920, sinv [64] @25984  -> total 26048 floats
// ---------------------------------------------------------------------------
#define SH_STRIDE  132
#define SWT_STRIDE 68
#define SA_STRIDE  68
#define SWH_STRIDE 68
#define OFF_WT  8448
#define OFF_A   17152
#define OFF_WH  21504
#define OFF_PR  25856
#define OFF_PS  25920
#define OFF_INV 25984
#define SMEM_FLOATS 26048

__global__ void __launch_bounds__(128, 2)
fused_kernel(const float* __restrict__ h,    // [B][N][T][FH]
             const float* __restrict__ W,    // [FO][FH]
             const float* __restrict__ bfc,  // [FO]
             const float* __restrict__ ab_ptr,
             float* __restrict__ out, int B)
{
    extern __shared__ float sm[];
    float* sh   = sm;             // [64][132]
    float* swt  = sm + OFF_WT;    // [128][68]
    float* sa   = sm + OFF_A;     // [64][68]; sa[0..127]=wr, sa[128..255]=ws early
    float* swh  = sm + OFF_WH;    // [64][68]
    float* spr  = sm + OFF_PR;
    float* sps  = sm + OFF_PS;
    float* sinv = sm + OFF_INV;

    const int t   = blockIdx.x;
    const int b   = blockIdx.y;
    const int tid = threadIdx.x;

    // ---- Phase 1: stage ----
    {   // h rows: warp per row-half, perfectly coalesced float4
        #pragma unroll
        for (int i = 0; i < 16; i++) {
            int idx = tid + i * 128;          // 0..2047
            int n = idx >> 5, c4 = (idx & 31) * 4;
            float4 v = *reinterpret_cast<const float4*>(
                h + ((size_t)(b * N_ + n) * T_ + t) * FH_ + c4);
            *reinterpret_cast<float4*>(&sh[n * SH_STRIDE + c4]) = v;
        }
    }
    {   // W^T: [k][o]
        int o = tid >> 1, kc = (tid & 1) * 64;
        const float4* wrow = reinterpret_cast<const float4*>(W + o * FH_ + kc);
        #pragma unroll
        for (int j = 0; j < 16; j++) {
            float4 v = wrow[j];
            int k = kc + j * 4;
            swt[(k + 0) * SWT_STRIDE + o] = v.x;
            swt[(k + 1) * SWT_STRIDE + o] = v.y;
            swt[(k + 2) * SWT_STRIDE + o] = v.z;
            swt[(k + 3) * SWT_STRIDE + o] = v.w;
        }
    }
    sa[tid]       = g_wr[tid & 127];   // wr into sa[0..127]
    sa[128 + tid] = g_ws[tid & 127];   // ws into sa[128..255]
    __syncthreads();

    // ---- Phase 2a: pr/ps (warps 0-1 -> pr, warps 2-3 -> ps) ----
    {
        int n = tid & 63;
        const float* hr = sh + n * SH_STRIDE;
        const float* wv = (tid < 64) ? sa : (sa + 128);
        float a = (tid < 64) ? g_cr : g_cs;
        #pragma unroll
        for (int k4 = 0; k4 < 32; k4++) {
            float4 hv = *reinterpret_cast<const float4*>(hr + k4 * 4);
            float4 wvv = *reinterpret_cast<const float4*>(wv + k4 * 4);
            a = fmaf(hv.x, wvv.x, a); a = fmaf(hv.y, wvv.y, a);
            a = fmaf(hv.z, wvv.z, a); a = fmaf(hv.w, wvv.w, a);
        }
        if (tid < 64) spr[n] = a; else sps[n] = a;
    }

    // ---- Phase 2b: GEMM1  Wh[n][o] = sum_k h[n][k] * W^T[k][o] + b[o] ----
    const int ni = tid >> 3;     // 0..15 -> rows ni*4 .. ni*4+3
    const int oi = tid & 7;      // 0..7  -> cols oi*8 .. oi*8+7
    const int o0 = oi * 8;
    {
        unsigned long long acc[16];
        #pragma unroll
        for (int c = 0; c < 4; c++) {
            unsigned long long bv = pack2(bfc[o0 + 2 * c], bfc[o0 + 2 * c + 1]);
            acc[c] = bv; acc[4 + c] = bv; acc[8 + c] = bv; acc[12 + c] = bv;
        }
        const float* hb = sh + (ni * 4) * SH_STRIDE;
        #pragma unroll 2
        for (int k4 = 0; k4 < 32; k4++) {
            float a0[4], a1[4], a2[4], a3[4];
            *reinterpret_cast<float4*>(a0) = *reinterpret_cast<const float4*>(hb + 0 * SH_STRIDE + k4 * 4);
            *reinterpret_cast<float4*>(a1) = *reinterpret_cast<const float4*>(hb + 1 * SH_STRIDE + k4 * 4);
            *reinterpret_cast<float4*>(a2) = *reinterpret_cast<const float4*>(hb + 2 * SH_STRIDE + k4 * 4);
            *reinterpret_cast<float4*>(a3) = *reinterpret_cast<const float4*>(hb + 3 * SH_STRIDE + k4 * 4);
            #pragma unroll
            for (int kk = 0; kk < 4; kk++) {
                const float* wk = swt + (k4 * 4 + kk) * SWT_STRIDE + o0;
                ulonglong2 w0 = *reinterpret_cast<const ulonglong2*>(wk);
                ulonglong2 w1 = *reinterpret_cast<const ulonglong2*>(wk + 4);
                unsigned long long h0 = pack2(a0[kk], a0[kk]);
                unsigned long long h1 = pack2(a1[kk], a1[kk]);
                unsigned long long h2 = pack2(a2[kk], a2[kk]);
                unsigned long long h3 = pack2(a3[kk], a3[kk]);
                acc[0]  = fma2(h0, w0.x, acc[0]);  acc[1]  = fma2(h0, w0.y, acc[1]);
                acc[2]  = fma2(h0, w1.x, acc[2]);  acc[3]  = fma2(h0, w1.y, acc[3]);
                acc[4]  = fma2(h1, w0.x, acc[4]);  acc[5]  = fma2(h1, w0.y, acc[5]);
                acc[6]  = fma2(h1, w1.x, acc[6]);  acc[7]  = fma2(h1, w1.y, acc[7]);
                acc[8]  = fma2(h2, w0.x, acc[8]);  acc[9]  = fma2(h2, w0.y, acc[9]);
                acc[10] = fma2(h2, w1.x, acc[10]); acc[11] = fma2(h2, w1.y, acc[11]);
                acc[12] = fma2(h3, w0.x, acc[12]); acc[13] = fma2(h3, w0.y, acc[13]);
                acc[14] = fma2(h3, w1.x, acc[14]); acc[15] = fma2(h3, w1.y, acc[15]);
            }
        }
        // store Wh tile to smem
        #pragma unroll
        for (int r = 0; r < 4; r++) {
            float* dst = swh + (ni * 4 + r) * SWH_STRIDE + o0;
            float4 v0 = make_float4(lo2(acc[r * 4 + 0]), hi2(acc[r * 4 + 0]),
                                    lo2(acc[r * 4 + 1]), hi2(acc[r * 4 + 1]));
            float4 v1 = make_float4(lo2(acc[r * 4 + 2]), hi2(acc[r * 4 + 2]),
                                    lo2(acc[r * 4 + 3]), hi2(acc[r * 4 + 3]));
            *reinterpret_cast<float4*>(dst)     = v0;
            *reinterpret_cast<float4*>(dst + 4) = v1;
        }
    }
    __syncthreads();

    // ---- Phase 3: scores into sA ----
    const float ab = ab_ptr[0];
    #pragma unroll
    for (int i = 0; i < 32; i++) {
        int idx = tid + i * 128;
        int r = idx >> 6, s = idx & 63;
        float c = g_cnt[idx];
        float v = 0.f;
        if (c != 0.f) {
            float x = spr[r] + sps[s] + ab;
            x = (x > 0.f) ? x : 0.2f * x;
            v = c * __expf(x);
        }
        sa[r * SA_STRIDE + s] = v;
    }
    __syncthreads();

    // ---- Phase 4: row sums + write A / A_sym ----
    if (tid < 64) {
        const float* row = sa + tid * SA_STRIDE;
        float s0 = 0.f, s1 = 0.f, s2 = 0.f, s3 = 0.f;
        #pragma unroll
        for (int j = 0; j < 16; j++) {
            float4 v = *reinterpret_cast<const float4*>(row + j * 4);
            s0 += v.x; s1 += v.y; s2 += v.z; s3 += v.w;
        }
        sinv[tid] = __fdividef(1.f, (s0 + s1) + (s2 + s3));
    }

    const size_t npp = (size_t)B * T_ * N_ * N_;
    float* A_out     = out + (size_t)B * N_ * T_ * FO_;
    float* Asym_out  = A_out + npp;
    float* Anorm_out = Asym_out + npp;
    const size_t abase = ((size_t)(b * T_ + t)) * (N_ * N_);

    #pragma unroll
    for (int i = 0; i < 32; i++) {
        int idx = tid + i * 128;
        int r = idx >> 6, s = idx & 63;
        float v = sa[r * SA_STRIDE + s];
        A_out[abase + idx]    = v;
        Asym_out[abase + idx] = 0.5f * (v + sa[s * SA_STRIDE + r]);
    }
    __syncthreads();

    // normalize in place + write A_norm
    #pragma unroll
    for (int i = 0; i < 32; i++) {
        int idx = tid + i * 128;
        int r = idx >> 6, s = idx & 63;
        float v = sa[r * SA_STRIDE + s] * sinv[r];
        Anorm_out[abase + idx] = v;
        sa[r * SA_STRIDE + s] = v;
    }
    __syncthreads();

    // ---- Phase 5: GEMM2  h_p[n][o] = relu( sum_m Anorm[n][m] * Wh[m][o] ) ----
    {
        unsigned long long acc[16];
        #pragma unroll
        for (int i = 0; i < 16; i++) acc[i] = 0ull;

        const float* arow = sa + (ni * 4) * SA_STRIDE;
        #pragma unroll 2
        for (int m4 = 0; m4 < 16; m4++) {
            float a0[4], a1[4], a2[4], a3[4];
            *reinterpret_cast<float4*>(a0) = *reinterpret_cast<const float4*>(arow + 0 * SA_STRIDE + m4 * 4);
            *reinterpret_cast<float4*>(a1) = *reinterpret_cast<const float4*>(arow + 1 * SA_STRIDE + m4 * 4);
            *reinterpret_cast<float4*>(a2) = *reinterpret_cast<const float4*>(arow + 2 * SA_STRIDE + m4 * 4);
            *reinterpret_cast<float4*>(a3) = *reinterpret_cast<const float4*>(arow + 3 * SA_STRIDE + m4 * 4);
            #pragma unroll
            for (int mm = 0; mm < 4; mm++) {
                const float* wm = swh + (m4 * 4 + mm) * SWH_STRIDE + o0;
                ulonglong2 w0 = *reinterpret_cast<const ulonglong2*>(wm);
                ulonglong2 w1 = *reinterpret_cast<const ulonglong2*>(wm + 4);
                unsigned long long h0 = pack2(a0[mm], a0[mm]);
                unsigned long long h1 = pack2(a1[mm], a1[mm]);
                unsigned long long h2 = pack2(a2[mm], a2[mm]);
                unsigned long long h3 = pack2(a3[mm], a3[mm]);
                acc[0]  = fma2(h0, w0.x, acc[0]);  acc[1]  = fma2(h0, w0.y, acc[1]);
                acc[2]  = fma2(h0, w1.x, acc[2]);  acc[3]  = fma2(h0, w1.y, acc[3]);
                acc[4]  = fma2(h1, w0.x, acc[4]);  acc[5]  = fma2(h1, w0.y, acc[5]);
                acc[6]  = fma2(h1, w1.x, acc[6]);  acc[7]  = fma2(h1, w1.y, acc[7]);
                acc[8]  = fma2(h2, w0.x, acc[8]);  acc[9]  = fma2(h2, w0.y, acc[9]);
                acc[10] = fma2(h2, w1.x, acc[10]); acc[11] = fma2(h2, w1.y, acc[11]);
                acc[12] = fma2(h3, w0.x, acc[12]); acc[13] = fma2(h3, w0.y, acc[13]);
                acc[14] = fma2(h3, w1.x, acc[14]); acc[15] = fma2(h3, w1.y, acc[15]);
            }
        }
        #pragma unroll
        for (int r = 0; r < 4; r++) {
            int n = ni * 4 + r;
            float* hp = out + (size_t)b * (N_ * T_ * FO_) + (size_t)n * (T_ * FO_)
                        + (size_t)t * FO_ + o0;
            float4 v0 = make_float4(fmaxf(lo2(acc[r * 4 + 0]), 0.f),
                                    fmaxf(hi2(acc[r * 4 + 0]), 0.f),
                                    fmaxf(lo2(acc[r * 4 + 1]), 0.f),
                                    fmaxf(hi2(acc[r * 4 + 1]), 0.f));
            float4 v1 = make_float4(fmaxf(lo2(acc[r * 4 + 2]), 0.f),
                                    fmaxf(hi2(acc[r * 4 + 2]), 0.f),
                                    fmaxf(lo2(acc[r * 4 + 3]), 0.f),
                                    fmaxf(hi2(acc[r * 4 + 3]), 0.f));
            *reinterpret_cast<float4*>(hp)     = v0;
            *reinterpret_cast<float4*>(hp + 4) = v1;
        }
    }
}

// ---------------------------------------------------------------------------
extern "C" void kernel_launch(void* const* d_in, const int* in_sizes, int n_in,
                              void* d_out, int out_size)
{
    const float* h   = (const float*)d_in[0];
    const float* rr  = (const float*)d_in[1];
    const float* rs  = (const float*)d_in[2];
    const float* Wfc = (const float*)d_in[3];
    const float* bfc = (const float*)d_in[4];
    const float* aw  = (const float*)d_in[5];
    const float* abp = (const float*)d_in[6];

    const int B = in_sizes[0] / (N_ * T_ * FH_);
    const int E = in_sizes[1] / N_;

    static bool attr_done = false;
    const int fused_smem = SMEM_FLOATS * sizeof(float);   // 104,192 B
    if (!attr_done) {
        cudaFuncSetAttribute(fused_kernel, cudaFuncAttributeMaxDynamicSharedMemorySize,
                             fused_smem);
        attr_done = true;
    }

    prep_kernel<<<1, 128>>>(Wfc, bfc, aw);
    edge_kernel<<<(E + 127) / 128, 128>>>(rr, rs, E);
    fused_kernel<<<dim3(T_, B), 128, fused_smem>>>(h, Wfc, bfc, abp, (float*)d_out, B);
}

// round 14
// speedup vs baseline: 1.5231x; 1.0253x over previous
#include <cuda_runtime.h>
#include <math.h>

// Shapes (fixed by setup_inputs): B=4, N=64, T=64, FH=128, FO=64
#define N_  64
#define T_  64
#define FH_ 128
#define FO_ 64

// Scratch (device global; no allocation allowed). Every element [0,E) is
// overwritten by edge_kernel each launch -> no zeroing needed.
__device__ int g_eidx[4096];

// ---------------------------------------------------------------------------
// packed fp32x2 helpers (Blackwell FFMA2 — only reachable via PTX)
// ---------------------------------------------------------------------------
__device__ __forceinline__ unsigned long long fma2(unsigned long long a,
                                                   unsigned long long b,
                                                   unsigned long long c) {
    unsigned long long d;
    asm("fma.rn.f32x2 %0, %1, %2, %3;" : "=l"(d) : "l"(a), "l"(b), "l"(c));
    return d;
}
__device__ __forceinline__ unsigned long long pack2(float x, float y) {
    unsigned long long d;
    asm("mov.b64 %0, {%1, %2};" : "=l"(d)
        : "r"(__float_as_uint(x)), "r"(__float_as_uint(y)));
    return d;
}
__device__ __forceinline__ float lo2(unsigned long long v) {
    return __uint_as_float((unsigned)v);
}
__device__ __forceinline__ float hi2(unsigned long long v) {
    return __uint_as_float((unsigned)(v >> 32));
}

// ---------------------------------------------------------------------------
// Kernel 1: edge indices via argmax (float4 loads, first-max rule).
// Plain stores (no atomics, no pre-zero).
// ---------------------------------------------------------------------------
__global__ void edge_kernel(const float* __restrict__ rr,
                            const float* __restrict__ rs, int E)
{
    int e = blockIdx.x * blockDim.x + threadIdx.x;
    if (e >= E) return;
    const float4* r4 = reinterpret_cast<const float4*>(rr) + (size_t)e * 16;
    const float4* s4 = reinterpret_cast<const float4*>(rs) + (size_t)e * 16;
    float mr = -1e30f, ms = -1e30f;
    int ir = 0, is = 0;
    #pragma unroll
    for (int j = 0; j < 16; j++) {
        float4 v = r4[j];
        if (v.x > mr) { mr = v.x; ir = j * 4 + 0; }
        if (v.y > mr) { mr = v.y; ir = j * 4 + 1; }
        if (v.z > mr) { mr = v.z; ir = j * 4 + 2; }
        if (v.w > mr) { mr = v.w; ir = j * 4 + 3; }
        float4 w = s4[j];
        if (w.x > ms) { ms = w.x; is = j * 4 + 0; }
        if (w.y > ms) { ms = w.y; is = j * 4 + 1; }
        if (w.z > ms) { ms = w.z; is = j * 4 + 2; }
        if (w.w > ms) { ms = w.w; is = j * 4 + 3; }
    }
    g_eidx[e] = ir * N_ + is;
}

// ---------------------------------------------------------------------------
// Kernel 2: FUSED. One block per (b,t), 128 threads.
//   P1: stage h[b,:,t,:], W^T, a_w ; zero score tile
//   P2: GEMM1  Wh = h @ W^T + b  -> swh
//   P3: pr/ps = swh · a_r / a_s   (bias folded in via Wh)
//   P4: edge scatter: sa[r][s] += exp(lrelu(pr[r]+ps[s]+ab))  (smem atomics)
//   P5: row sums ; write A / A_sym ; normalize -> A_norm
//   P6: GEMM2  h_p = relu(A_norm @ Wh)
// ---------------------------------------------------------------------------
#define SH_STRIDE  132
#define SWT_STRIDE 68
#define SA_STRIDE  68
#define SWH_STRIDE 68
#define OFF_WT  8448                  // after sh [64][132]
#define OFF_A   (OFF_WT + 128*68)     // 17152
#define OFF_WH  (OFF_A + 64*68)       // 21504
#define OFF_PR  (OFF_WH + 64*68)      // 25856
#define OFF_PS  (OFF_PR + 64)
#define OFF_INV (OFF_PS + 64)
#define OFF_AW  (OFF_INV + 64)
#define SMEM_FLOATS (OFF_AW + 128)    // 26176 floats = 104704 B

__global__ void __launch_bounds__(128, 2)
fused_kernel(const float* __restrict__ h,    // [B][N][T][FH]
             const float* __restrict__ W,    // [FO][FH]
             const float* __restrict__ bfc,  // [FO]
             const float* __restrict__ aw,   // [2*FO]
             const float* __restrict__ ab_ptr,
             float* __restrict__ out, int B, int E)
{
    extern __shared__ float sm[];
    float* sh   = sm;             // [64][132]
    float* swt  = sm + OFF_WT;    // [128][68]
    float* sa   = sm + OFF_A;     // [64][68]
    float* swh  = sm + OFF_WH;    // [64][68]
    float* spr  = sm + OFF_PR;
    float* sps  = sm + OFF_PS;
    float* sinv = sm + OFF_INV;
    float* saw  = sm + OFF_AW;    // [128]

    const int t   = blockIdx.x;
    const int b   = blockIdx.y;
    const int tid = threadIdx.x;

    // ---- P1: stage ----
    #pragma unroll
    for (int i = 0; i < 16; i++) {
        int idx = tid + i * 128;          // 0..2047
        int n = idx >> 5, c4 = (idx & 31) * 4;
        float4 v = *reinterpret_cast<const float4*>(
            h + ((size_t)(b * N_ + n) * T_ + t) * FH_ + c4);
        *reinterpret_cast<float4*>(&sh[n * SH_STRIDE + c4]) = v;
    }
    {   // W^T: [k][o]
        int o = tid >> 1, kc = (tid & 1) * 64;
        const float4* wrow = reinterpret_cast<const float4*>(W + o * FH_ + kc);
        #pragma unroll
        for (int j = 0; j < 16; j++) {
            float4 v = wrow[j];
            int k = kc + j * 4;
            swt[(k + 0) * SWT_STRIDE + o] = v.x;
            swt[(k + 1) * SWT_STRIDE + o] = v.y;
            swt[(k + 2) * SWT_STRIDE + o] = v.z;
            swt[(k + 3) * SWT_STRIDE + o] = v.w;
        }
    }
    saw[tid] = aw[tid];
    #pragma unroll
    for (int i = 0; i < 34; i++) sa[tid + i * 128] = 0.f;   // 64*68 = 4352
    __syncthreads();

    // ---- P2: GEMM1  Wh[n][o] = sum_k h[n][k] * W^T[k][o] + b[o] ----
    const int ni = tid >> 3;     // 0..15 -> rows ni*4 .. ni*4+3
    const int oi = tid & 7;      // 0..7  -> cols oi*8 .. oi*8+7
    const int o0 = oi * 8;
    {
        unsigned long long acc[16];
        #pragma unroll
        for (int c = 0; c < 4; c++) {
            unsigned long long bv = pack2(bfc[o0 + 2 * c], bfc[o0 + 2 * c + 1]);
            acc[c] = bv; acc[4 + c] = bv; acc[8 + c] = bv; acc[12 + c] = bv;
        }
        const float* hb = sh + (ni * 4) * SH_STRIDE;
        #pragma unroll 2
        for (int k4 = 0; k4 < 32; k4++) {
            float a0[4], a1[4], a2[4], a3[4];
            *reinterpret_cast<float4*>(a0) = *reinterpret_cast<const float4*>(hb + 0 * SH_STRIDE + k4 * 4);
            *reinterpret_cast<float4*>(a1) = *reinterpret_cast<const float4*>(hb + 1 * SH_STRIDE + k4 * 4);
            *reinterpret_cast<float4*>(a2) = *reinterpret_cast<const float4*>(hb + 2 * SH_STRIDE + k4 * 4);
            *reinterpret_cast<float4*>(a3) = *reinterpret_cast<const float4*>(hb + 3 * SH_STRIDE + k4 * 4);
            #pragma unroll
            for (int kk = 0; kk < 4; kk++) {
                const float* wk = swt + (k4 * 4 + kk) * SWT_STRIDE + o0;
                ulonglong2 w0 = *reinterpret_cast<const ulonglong2*>(wk);
                ulonglong2 w1 = *reinterpret_cast<const ulonglong2*>(wk + 4);
                unsigned long long h0 = pack2(a0[kk], a0[kk]);
                unsigned long long h1 = pack2(a1[kk], a1[kk]);
                unsigned long long h2 = pack2(a2[kk], a2[kk]);
                unsigned long long h3 = pack2(a3[kk], a3[kk]);
                acc[0]  = fma2(h0, w0.x, acc[0]);  acc[1]  = fma2(h0, w0.y, acc[1]);
                acc[2]  = fma2(h0, w1.x, acc[2]);  acc[3]  = fma2(h0, w1.y, acc[3]);
                acc[4]  = fma2(h1, w0.x, acc[4]);  acc[5]  = fma2(h1, w0.y, acc[5]);
                acc[6]  = fma2(h1, w1.x, acc[6]);  acc[7]  = fma2(h1, w1.y, acc[7]);
                acc[8]  = fma2(h2, w0.x, acc[8]);  acc[9]  = fma2(h2, w0.y, acc[9]);
                acc[10] = fma2(h2, w1.x, acc[10]); acc[11] = fma2(h2, w1.y, acc[11]);
                acc[12] = fma2(h3, w0.x, acc[12]); acc[13] = fma2(h3, w0.y, acc[13]);
                acc[14] = fma2(h3, w1.x, acc[14]); acc[15] = fma2(h3, w1.y, acc[15]);
            }
        }
        #pragma unroll
        for (int r = 0; r < 4; r++) {
            float* dst = swh + (ni * 4 + r) * SWH_STRIDE + o0;
            float4 v0 = make_float4(lo2(acc[r * 4 + 0]), hi2(acc[r * 4 + 0]),
                                    lo2(acc[r * 4 + 1]), hi2(acc[r * 4 + 1]));
            float4 v1 = make_float4(lo2(acc[r * 4 + 2]), hi2(acc[r * 4 + 2]),
                                    lo2(acc[r * 4 + 3]), hi2(acc[r * 4 + 3]));
            *reinterpret_cast<float4*>(dst)     = v0;
            *reinterpret_cast<float4*>(dst + 4) = v1;
        }
    }
    __syncthreads();

    // ---- P3: pr/ps from Wh (bias already folded in) ----
    {
        int n = tid & 63;
        const float* wr = swh + n * SWH_STRIDE;
        const float* av = (tid < 64) ? saw : (saw + 64);
        float a = 0.f;
        #pragma unroll
        for (int j = 0; j < 16; j++) {
            float4 wv = *reinterpret_cast<const float4*>(wr + j * 4);
            float4 avv = *reinterpret_cast<const float4*>(av + j * 4);
            a = fmaf(wv.x, avv.x, a); a = fmaf(wv.y, avv.y, a);
            a = fmaf(wv.z, avv.z, a); a = fmaf(wv.w, avv.w, a);
        }
        if (tid < 64) spr[n] = a; else sps[n] = a;
    }
    __syncthreads();

    // ---- P4: edge scatter into sa ----
    const float ab = ab_ptr[0];
    for (int e = tid; e < E; e += 128) {
        int idx = g_eidx[e];
        int r = idx >> 6, s = idx & 63;
        float x = spr[r] + sps[s] + ab;
        x = (x > 0.f) ? x : 0.2f * x;
        atomicAdd(&sa[r * SA_STRIDE + s], __expf(x));
    }
    __syncthreads();

    // ---- P5: row sums, write A / A_sym, normalize -> A_norm ----
    if (tid < 64) {
        const float* row = sa + tid * SA_STRIDE;
        float s0 = 0.f, s1 = 0.f, s2 = 0.f, s3 = 0.f;
        #pragma unroll
        for (int j = 0; j < 16; j++) {
            float4 v = *reinterpret_cast<const float4*>(row + j * 4);
            s0 += v.x; s1 += v.y; s2 += v.z; s3 += v.w;
        }
        sinv[tid] = __fdividef(1.f, (s0 + s1) + (s2 + s3));
    }

    const size_t npp = (size_t)B * T_ * N_ * N_;
    float* A_out     = out + (size_t)B * N_ * T_ * FO_;
    float* Asym_out  = A_out + npp;
    float* Anorm_out = Asym_out + npp;
    const size_t abase = ((size_t)(b * T_ + t)) * (N_ * N_);

    #pragma unroll
    for (int i = 0; i < 32; i++) {
        int idx = tid + i * 128;
        int r = idx >> 6, s = idx & 63;
        float v = sa[r * SA_STRIDE + s];
        A_out[abase + idx]    = v;
        Asym_out[abase + idx] = 0.5f * (v + sa[s * SA_STRIDE + r]);
    }
    __syncthreads();

    #pragma unroll
    for (int i = 0; i < 32; i++) {
        int idx = tid + i * 128;
        int r = idx >> 6, s = idx & 63;
        float v = sa[r * SA_STRIDE + s] * sinv[r];
        Anorm_out[abase + idx] = v;
        sa[r * SA_STRIDE + s] = v;
    }
    __syncthreads();

    // ---- P6: GEMM2  h_p[n][o] = relu( sum_m Anorm[n][m] * Wh[m][o] ) ----
    {
        unsigned long long acc[16];
        #pragma unroll
        for (int i = 0; i < 16; i++) acc[i] = 0ull;

        const float* arow = sa + (ni * 4) * SA_STRIDE;
        #pragma unroll 2
        for (int m4 = 0; m4 < 16; m4++) {
            float a0[4], a1[4], a2[4], a3[4];
            *reinterpret_cast<float4*>(a0) = *reinterpret_cast<const float4*>(arow + 0 * SA_STRIDE + m4 * 4);
            *reinterpret_cast<float4*>(a1) = *reinterpret_cast<const float4*>(arow + 1 * SA_STRIDE + m4 * 4);
            *reinterpret_cast<float4*>(a2) = *reinterpret_cast<const float4*>(arow + 2 * SA_STRIDE + m4 * 4);
            *reinterpret_cast<float4*>(a3) = *reinterpret_cast<const float4*>(arow + 3 * SA_STRIDE + m4 * 4);
            #pragma unroll
            for (int mm = 0; mm < 4; mm++) {
                const float* wm = swh + (m4 * 4 + mm) * SWH_STRIDE + o0;
                ulonglong2 w0 = *reinterpret_cast<const ulonglong2*>(wm);
                ulonglong2 w1 = *reinterpret_cast<const ulonglong2*>(wm + 4);
                unsigned long long h0 = pack2(a0[mm], a0[mm]);
                unsigned long long h1 = pack2(a1[mm], a1[mm]);
                unsigned long long h2 = pack2(a2[mm], a2[mm]);
                unsigned long long h3 = pack2(a3[mm], a3[mm]);
                acc[0]  = fma2(h0, w0.x, acc[0]);  acc[1]  = fma2(h0, w0.y, acc[1]);
                acc[2]  = fma2(h0, w1.x, acc[2]);  acc[3]  = fma2(h0, w1.y, acc[3]);
                acc[4]  = fma2(h1, w0.x, acc[4]);  acc[5]  = fma2(h1, w0.y, acc[5]);
                acc[6]  = fma2(h1, w1.x, acc[6]);  acc[7]  = fma2(h1, w1.y, acc[7]);
                acc[8]  = fma2(h2, w0.x, acc[8]);  acc[9]  = fma2(h2, w0.y, acc[9]);
                acc[10] = fma2(h2, w1.x, acc[10]); acc[11] = fma2(h2, w1.y, acc[11]);
                acc[12] = fma2(h3, w0.x, acc[12]); acc[13] = fma2(h3, w0.y, acc[13]);
                acc[14] = fma2(h3, w1.x, acc[14]); acc[15] = fma2(h3, w1.y, acc[15]);
            }
        }
        #pragma unroll
        for (int r = 0; r < 4; r++) {
            int n = ni * 4 + r;
            float* hp = out + (size_t)b * (N_ * T_ * FO_) + (size_t)n * (T_ * FO_)
                        + (size_t)t * FO_ + o0;
            float4 v0 = make_float4(fmaxf(lo2(acc[r * 4 + 0]), 0.f),
                                    fmaxf(hi2(acc[r * 4 + 0]), 0.f),
                                    fmaxf(lo2(acc[r * 4 + 1]), 0.f),
                                    fmaxf(hi2(acc[r * 4 + 1]), 0.f));
            float4 v1 = make_float4(fmaxf(lo2(acc[r * 4 + 2]), 0.f),
                                    fmaxf(hi2(acc[r * 4 + 2]), 0.f),
                                    fmaxf(lo2(acc[r * 4 + 3]), 0.f),
                                    fmaxf(hi2(acc[r * 4 + 3]), 0.f));
            *reinterpret_cast<float4*>(hp)     = v0;
            *reinterpret_cast<float4*>(hp + 4) = v1;
        }
    }
}

// ---------------------------------------------------------------------------
extern "C" void kernel_launch(void* const* d_in, const int* in_sizes, int n_in,
                              void* d_out, int out_size)
{
    const float* h   = (const float*)d_in[0];
    const float* rr  = (const float*)d_in[1];
    const float* rs  = (const float*)d_in[2];
    const float* Wfc = (const float*)d_in[3];
    const float* bfc = (const float*)d_in[4];
    const float* aw  = (const float*)d_in[5];
    const float* abp = (const float*)d_in[6];

    const int B = in_sizes[0] / (N_ * T_ * FH_);
    const int E = in_sizes[1] / N_;

    static bool attr_done = false;
    const int fused_smem = SMEM_FLOATS * sizeof(float);   // 104,704 B
    if (!attr_done) {
        cudaFuncSetAttribute(fused_kernel, cudaFuncAttributeMaxDynamicSharedMemorySize,
                             fused_smem);
        attr_done = true;
    }

    edge_kernel<<<(E + 127) / 128, 128>>>(rr, rs, E);
    fused_kernel<<<dim3(T_, B), 128, fused_smem>>>(h, Wfc, bfc, aw, abp,
                                                   (float*)d_out, B, E);
}